// round 16
// baseline (speedup 1.0000x reference)
#include <cuda_runtime.h>
#include <cstdint>

// ComplexSuperposition: B=128, T=128, D=512
// reduce_k: proven 512-block weighted reduction (+PDL trigger).
// outer_k : outer products computed into SMEM planes, streamed to GMEM via
//           TMA bulk stores (cp.async.bulk) — bypasses STG issue / L1 wavefront
//           limits that pinned the STG version at ~5.2 TB/s.
// d_out: [output_r (128*512*512 f32)][output_i (...)]

#define BB 128
#define TT 128
#define DD 512

__device__ float g_outr[BB * DD];
__device__ float g_outi[BB * DD];

__device__ __forceinline__ uint32_t smem_u32(const void* p) {
    uint32_t a;
    asm("{ .reg .u64 t; cvta.to.shared.u64 t, %1; cvt.u32.u64 %0, t; }"
        : "=r"(a) : "l"(p));
    return a;
}

// ───────── reduce: 512 blocks × 256 threads (round-3 proven) ─────────
__global__ void __launch_bounds__(256) reduce_k(const float* __restrict__ re,
                                                const float* __restrict__ im,
                                                const float* __restrict__ w) {
    __shared__ float4 sr[8][32];
    __shared__ float4 si[8][32];

    int b     = blockIdx.x >> 2;
    int chunk = blockIdx.x & 3;
    int tid   = threadIdx.x;
    int j     = tid & 31;
    int tg    = tid >> 5;

    size_t base4 = ((size_t)b * TT * DD + chunk * 128 + j * 4) >> 2;
    const float4* rp = (const float4*)re + base4;
    const float4* ip = (const float4*)im + base4;
    const float*  wp = w + b * TT;

    float4 ar = make_float4(0.f, 0.f, 0.f, 0.f);
    float4 ai = make_float4(0.f, 0.f, 0.f, 0.f);

    int t0 = tg * 16;
#pragma unroll 16
    for (int k = 0; k < 16; ++k) {
        int t = t0 + k;
        float  wt = __ldg(wp + t);
        float4 r  = __ldg(rp + (size_t)t * (DD / 4));
        float4 m  = __ldg(ip + (size_t)t * (DD / 4));
        ar.x = fmaf(r.x, wt, ar.x);  ar.y = fmaf(r.y, wt, ar.y);
        ar.z = fmaf(r.z, wt, ar.z);  ar.w = fmaf(r.w, wt, ar.w);
        ai.x = fmaf(m.x, wt, ai.x);  ai.y = fmaf(m.y, wt, ai.y);
        ai.z = fmaf(m.z, wt, ai.z);  ai.w = fmaf(m.w, wt, ai.w);
    }
    sr[tg][j] = ar;
    si[tg][j] = ai;
    __syncthreads();

    if (tid < 64) {
        int q = tid >> 5;
        int l = tid & 31;
        float4 acc = make_float4(0.f, 0.f, 0.f, 0.f);
#pragma unroll
        for (int k = 0; k < 8; ++k) {
            float4 v = q ? si[k][l] : sr[k][l];
            acc.x += v.x; acc.y += v.y; acc.z += v.z; acc.w += v.w;
        }
        float4* dst = (float4*)(q ? g_outi : g_outr);
        dst[((size_t)b * DD + chunk * 128 + l * 4) >> 2] = acc;
        __threadfence();
    }
    __syncthreads();
#if __CUDA_ARCH__ >= 900
    cudaTriggerProgrammaticLaunchCompletion();
#endif
}

// ───────── outer: one block = (batch, 16-row tile); TMA bulk stores ─────────
// Dynamic smem layout (floats):
//   [0, 512)         out_r vector
//   [512, 1024)      out_i vector
//   [1024 + p*4096 + h*8192, ...)  plane p∈{r=0,i=1}, half h∈{0,1}, 8x512 each
__global__ void __launch_bounds__(256) outer_k(float* __restrict__ out) {
    extern __shared__ __align__(16) float smem[];
    float* s_vr   = smem;
    float* s_vi   = smem + 512;
    float* planes = smem + 1024;

    int b    = blockIdx.x >> 5;
    int tile = blockIdx.x & 31;
    int tid  = threadIdx.x;
    int j4   = tid & 127;
    int ih   = tid >> 7;

#if __CUDA_ARCH__ >= 900
    cudaGridDependencySynchronize();   // wait for reduce_k results
#endif

    if (tid < 128)      ((float4*)s_vr)[tid]       = ((const float4*)(g_outr + b * DD))[tid];
    else                ((float4*)s_vi)[tid - 128] = ((const float4*)(g_outi + b * DD))[tid - 128];
    __syncthreads();

    float4 br = ((const float4*)s_vr)[j4];
    float4 bi = ((const float4*)s_vi)[j4];

    const float* gr_base = out + (size_t)b * DD * DD + (size_t)(tile * 16) * DD;
    const float* gi_base = gr_base + (size_t)BB * DD * DD;

#pragma unroll
    for (int h = 0; h < 2; ++h) {
        float4* pr = (float4*)(planes + h * 8192);          // 8x512 r-plane
        float4* pi = (float4*)(planes + h * 8192 + 4096);   // 8x512 i-plane

#pragma unroll
        for (int k = 0; k < 4; ++k) {
            int row = k * 2 + ih;                // 0..7 within half
            int i   = tile * 16 + h * 8 + row;   // global row
            float arw = s_vr[i];
            float aiw = s_vi[i];
            float4 vr, vi;
            vr.x = fmaf(arw, br.x, aiw * bi.x);
            vr.y = fmaf(arw, br.y, aiw * bi.y);
            vr.z = fmaf(arw, br.z, aiw * bi.z);
            vr.w = fmaf(arw, br.w, aiw * bi.w);
            vi.x = fmaf(aiw, br.x, -arw * bi.x);
            vi.y = fmaf(aiw, br.y, -arw * bi.y);
            vi.z = fmaf(aiw, br.z, -arw * bi.z);
            vi.w = fmaf(aiw, br.w, -arw * bi.w);
            pr[row * 128 + j4] = vr;             // STS.128, conflict-free
            pi[row * 128 + j4] = vi;
        }
        __syncthreads();                          // plane complete
        if (tid == 0) {
            asm volatile("fence.proxy.async.shared::cta;" ::: "memory");
            uint32_t sr_a = smem_u32(pr);
            uint32_t si_a = smem_u32(pi);
            const float* gdr = gr_base + h * 8 * DD;
            const float* gdi = gi_base + h * 8 * DD;
            asm volatile("cp.async.bulk.global.shared::cta.bulk_group [%0], [%1], %2;"
                         :: "l"(gdr), "r"(sr_a), "r"(16384) : "memory");
            asm volatile("cp.async.bulk.global.shared::cta.bulk_group [%0], [%1], %2;"
                         :: "l"(gdi), "r"(si_a), "r"(16384) : "memory");
            asm volatile("cp.async.bulk.commit_group;" ::: "memory");
        }
        // no wait here: half 1 uses distinct buffers, overlaps half 0's drain
    }
    if (tid == 0)
        asm volatile("cp.async.bulk.wait_group 0;" ::: "memory");
}

extern "C" void kernel_launch(void* const* d_in, const int* in_sizes, int n_in,
                              void* d_out, int out_size) {
    const float* re = (const float*)d_in[0];   // input_real [128,128,512]
    const float* im = (const float*)d_in[1];   // input_imag [128,128,512]
    const float* w  = (const float*)d_in[2];   // weight     [128,128]

    reduce_k<<<BB * 4, 256>>>(re, im, w);

    constexpr int SMEM_BYTES = (1024 + 4 * 4096) * 4;   // 69632
    static int attr_set = 0;
    if (!attr_set) {   // host-side attribute, not a stream op; safe under capture
        cudaFuncSetAttribute(outer_k, cudaFuncAttributeMaxDynamicSharedMemorySize,
                             SMEM_BYTES);
        attr_set = 1;
    }

    cudaLaunchConfig_t cfg = {};
    cfg.gridDim  = dim3(BB * 32);
    cfg.blockDim = dim3(256);
    cfg.dynamicSmemBytes = SMEM_BYTES;
    cfg.stream = 0;
    cudaLaunchAttribute attr[1];
    attr[0].id = cudaLaunchAttributeProgrammaticStreamSerialization;
    attr[0].val.programmaticStreamSerializationAllowed = 1;
    cfg.attrs = attr;
    cfg.numAttrs = 1;
    cudaLaunchKernelEx(&cfg, outer_k, (float*)d_out);
}

// round 17
// speedup vs baseline: 1.0110x; 1.0110x over previous
#include <cuda_runtime.h>

// ComplexSuperposition: B=128, T=128, D=512
// LTS-cap analysis: reads (64MB) + writes (268MB) share the L2/LTS throughput
// ceiling (~6300 B/cyc, path-independent), so the floor is ~332MB/cap ≈ 51us.
// Strategy: ONE kernel launch (no prologue, no inter-kernel gap), R8-proven
// producer/consumer structure, self-resetting flags for graph replays.
//   blocks [0,512):    reducers, 4 per batch (resident in wave 1).
//   blocks [512,4608): outer-product streamers, 32 per batch, spin on flag.
// d_out: [output_r (128*512*512 f32)][output_i (...)]

#define BB 128
#define TT 128
#define DD 512
#define NRED (BB * 4)
#define NOUT (BB * 32)

__device__ float g_outr[BB * DD];
__device__ float g_outi[BB * DD];
__device__ int   g_ready[BB];   // 0 -> 4 by producers
__device__ int   g_done[BB];    // 0 -> 32 by consumers; 32nd resets both

__global__ void __launch_bounds__(256) main_k(const float* __restrict__ re,
                                              const float* __restrict__ im,
                                              const float* __restrict__ w,
                                              float* __restrict__ out) {
    __shared__ __align__(16) char smem_raw[8192];
    int bid = blockIdx.x;
    int tid = threadIdx.x;

    if (bid < NRED) {
        // ───────────────── reducer: 4 blocks per batch ─────────────────
        float4 (*sr)[32] = (float4(*)[32])(smem_raw);
        float4 (*si)[32] = (float4(*)[32])(smem_raw + 4096);

        int b     = bid >> 2;
        int chunk = bid & 3;          // 128-float chunk of D
        int j     = tid & 31;         // float4 lane
        int tg    = tid >> 5;         // T-split group (0..7), 16 t's each

        size_t base4 = ((size_t)b * TT * DD + chunk * 128 + j * 4) >> 2;
        const float4* rp = (const float4*)re + base4;
        const float4* ip = (const float4*)im + base4;
        const float*  wp = w + b * TT;

        float4 ar = make_float4(0.f, 0.f, 0.f, 0.f);
        float4 ai = make_float4(0.f, 0.f, 0.f, 0.f);

        int t0 = tg * 16;
#pragma unroll 16
        for (int k = 0; k < 16; ++k) {
            int t = t0 + k;
            float  wt = __ldg(wp + t);
            float4 r  = __ldg(rp + (size_t)t * (DD / 4));
            float4 m  = __ldg(ip + (size_t)t * (DD / 4));
            ar.x = fmaf(r.x, wt, ar.x);  ar.y = fmaf(r.y, wt, ar.y);
            ar.z = fmaf(r.z, wt, ar.z);  ar.w = fmaf(r.w, wt, ar.w);
            ai.x = fmaf(m.x, wt, ai.x);  ai.y = fmaf(m.y, wt, ai.y);
            ai.z = fmaf(m.z, wt, ai.z);  ai.w = fmaf(m.w, wt, ai.w);
        }
        sr[tg][j] = ar;
        si[tg][j] = ai;
        __syncthreads();

        if (tid < 64) {
            int q = tid >> 5;         // 0 = real, 1 = imag
            int l = tid & 31;
            float4 acc = make_float4(0.f, 0.f, 0.f, 0.f);
#pragma unroll
            for (int k = 0; k < 8; ++k) {
                float4 v = q ? si[k][l] : sr[k][l];
                acc.x += v.x; acc.y += v.y; acc.z += v.z; acc.w += v.w;
            }
            float4* dst = (float4*)(q ? g_outi : g_outr);
            dst[((size_t)b * DD + chunk * 128 + l * 4) >> 2] = acc;
        }
        // publish: data stores -> gpu fence -> barrier -> release arrive
        __threadfence();
        __syncthreads();
        if (tid == 0) atomicAdd(&g_ready[b], 1);

    } else {
        // ───────────────── outer: 32 blocks per batch ─────────────────
        float4* sr4 = (float4*)(smem_raw);          // 2 KB: out_r[b,:]
        float4* si4 = (float4*)(smem_raw + 2048);   // 2 KB: out_i[b,:]

        int obid = bid - NRED;
        int b    = obid >> 5;
        int tile = obid & 31;

        // address setup before the wait (free work)
        int j4 = tid & 127;
        int ih = tid >> 7;
        float4* outr = (float4*)(out + (size_t)b * DD * DD)
                       + (size_t)(tile * 16) * 128 + j4;
        float4* outi = outr + (size_t)BB * DD * DD / 4;

        if (tid == 0) {
            // cheap poll: volatile L2 read + backoff (no atomic RMW pressure)
            volatile int* rf = (volatile int*)&g_ready[b];
            int ns = 32;
            while (*rf < 4) {
                __nanosleep(ns);
                if (ns < 1024) ns <<= 1;
            }
            // consumed-count; the 32nd consumer resets both flags so the
            // next graph replay starts clean (all waiters have passed).
            if (atomicAdd(&g_done[b], 1) == 31) {
                g_ready[b] = 0;
                atomicExch(&g_done[b], 0);
            }
        }
        __syncthreads();
        __threadfence();   // acquire: order flag observation before data loads

        const float4* gr = (const float4*)(g_outr + b * DD);
        const float4* gi = (const float4*)(g_outi + b * DD);
        if (tid < 128) sr4[tid] = gr[tid];
        else           si4[tid - 128] = gi[tid - 128];
        __syncthreads();

        const float* srf = (const float*)sr4;
        const float* sif = (const float*)si4;

        float4 br = sr4[j4];
        float4 bi = si4[j4];

#pragma unroll
        for (int k = 0; k < 8; ++k) {
            int row = k * 2 + ih;
            int i   = tile * 16 + row;
            float arw = srf[i];
            float aiw = sif[i];
            float4 vr, vi;
            vr.x = fmaf(arw, br.x, aiw * bi.x);
            vr.y = fmaf(arw, br.y, aiw * bi.y);
            vr.z = fmaf(arw, br.z, aiw * bi.z);
            vr.w = fmaf(arw, br.w, aiw * bi.w);
            vi.x = fmaf(aiw, br.x, -arw * bi.x);
            vi.y = fmaf(aiw, br.y, -arw * bi.y);
            vi.z = fmaf(aiw, br.z, -arw * bi.z);
            vi.w = fmaf(aiw, br.w, -arw * bi.w);
            __stcs(&outr[(size_t)row * 128], vr);   // streaming: never re-read
            __stcs(&outi[(size_t)row * 128], vi);
        }
    }
}

extern "C" void kernel_launch(void* const* d_in, const int* in_sizes, int n_in,
                              void* d_out, int out_size) {
    const float* re = (const float*)d_in[0];   // input_real [128,128,512]
    const float* im = (const float*)d_in[1];   // input_imag [128,128,512]
    const float* w  = (const float*)d_in[2];   // weight     [128,128]
    float* out = (float*)d_out;                // [2,128,512,512]

    main_k<<<NRED + NOUT, 256>>>(re, im, w, out);
}